// round 7
// baseline (speedup 1.0000x reference)
#include <cuda_runtime.h>
#include <cuda_fp16.h>
#include <math.h>
#include <stdint.h>

// FullAttention B=4, L=S=2048, H=8, E=D=64, fp32 in/out.
// Flash attention, mma.sync.m16n8k16 fp16 + ldmatrix fragments.
// CTA = 128 threads (4 warps), Q tile 64 (16/warp), KV chunk 64.
// - K/V staged row-major fp16 (vectorized STS.128, conflict-free via 72-half pad)
// - all mma fragments via ldmatrix.x4 (V with .trans -> no transpose staging)
// - P kept in registers: S C-frag layout == PV A-frag layout

#define BM 64
#define BN 64
#define LDH 72   // halves; 144B rows -> banks 4r..4r+3 per 16B chunk, conflict-free

static constexpr int Bb = 4, Ll = 2048, Ss = 2048, Hh = 8, Ee = 64, Dd = 64;

__device__ __forceinline__ void mma_fp16(float* c, uint32_t a0, uint32_t a1,
                                         uint32_t a2, uint32_t a3,
                                         uint32_t b0, uint32_t b1) {
    asm volatile(
        "mma.sync.aligned.m16n8k16.row.col.f32.f16.f16.f32 "
        "{%0,%1,%2,%3}, {%4,%5,%6,%7}, {%8,%9}, {%0,%1,%2,%3};"
        : "+f"(c[0]), "+f"(c[1]), "+f"(c[2]), "+f"(c[3])
        : "r"(a0), "r"(a1), "r"(a2), "r"(a3), "r"(b0), "r"(b1));
}
__device__ __forceinline__ uint32_t h2u(__half2 h) { return *reinterpret_cast<uint32_t*>(&h); }

#define LDM_X4(r0, r1, r2, r3, a)                                              \
    asm volatile("ldmatrix.sync.aligned.m8n8.x4.shared.b16 {%0,%1,%2,%3}, [%4];" \
        : "=r"(r0), "=r"(r1), "=r"(r2), "=r"(r3) : "r"(a))
#define LDM_X4T(r0, r1, r2, r3, a)                                             \
    asm volatile("ldmatrix.sync.aligned.m8n8.x4.trans.shared.b16 {%0,%1,%2,%3}, [%4];" \
        : "=r"(r0), "=r"(r1), "=r"(r2), "=r"(r3) : "r"(a))

__global__ __launch_bounds__(128, 3)
void flash_fp16(const float* __restrict__ Q, const float* __restrict__ K,
                const float* __restrict__ V, float* __restrict__ Out)
{
    __shared__ __align__(16) __half sQ[BM * LDH];
    __shared__ __align__(16) __half sK[BN * LDH];
    __shared__ __align__(16) __half sV[BN * LDH];   // row-major [s][d]

    const int tid  = threadIdx.x;
    const int lane = tid & 31;
    const int warp = tid >> 5;
    const int mbase = warp * 16;

    const int qtile = blockIdx.x, h = blockIdx.y, b = blockIdx.z;
    const int q0 = qtile * BM;
    const int gs = Hh * Ee;        // 512

    const float* Qb = Q + ((size_t)(b * Ll + q0) * Hh + h) * Ee;
    const float* Kb = K + ((size_t)b * Ss * Hh + h) * Ee;
    const float* Vb = V + ((size_t)b * Ss * Hh + h) * Dd;

    // staging: thread -> (row, 32-col half)
    const int srow  = tid >> 1;
    const int shalf = tid & 1;

    // ---- Stage Q once (scaled -> fp16)
    {
        const float4* src = reinterpret_cast<const float4*>(Qb + (size_t)srow * gs + shalf * 32);
        __half2 hh[16];
        #pragma unroll
        for (int i = 0; i < 8; i++) {
            float4 f = src[i];
            hh[2 * i]     = __floats2half2_rn(f.x * 0.125f, f.y * 0.125f);
            hh[2 * i + 1] = __floats2half2_rn(f.z * 0.125f, f.w * 0.125f);
        }
        uint4* dst = reinterpret_cast<uint4*>(&sQ[srow * LDH + shalf * 32]);
        #pragma unroll
        for (int j = 0; j < 4; j++) dst[j] = reinterpret_cast<uint4*>(hh)[j];
    }

    float acc_o[8][4];
    float m_run[2] = {-INFINITY, -INFINITY};
    float l_run[2] = {0.f, 0.f};
    #pragma unroll
    for (int n = 0; n < 8; n++)
        #pragma unroll
        for (int j = 0; j < 4; j++) acc_o[n][j] = 0.f;

    // per-lane ldmatrix address components
    const int lrow = lane & 15;            // row within 16-row block
    const int lcol = (lane >> 4) * 8;      // 8-half col offset for matrices 2,3

    for (int s0 = 0; s0 < Ss; s0 += BN) {
        __syncthreads();   // previous tile's fragment reads done

        // ---- Stage K,V (row-major fp16, vectorized)
        {
            const float4* ksrc = reinterpret_cast<const float4*>(Kb + (size_t)(s0 + srow) * gs + shalf * 32);
            const float4* vsrc = reinterpret_cast<const float4*>(Vb + (size_t)(s0 + srow) * gs + shalf * 32);
            __half2 kh[16], vh[16];
            #pragma unroll
            for (int i = 0; i < 8; i++) {
                float4 kf = ksrc[i];
                kh[2 * i]     = __floats2half2_rn(kf.x, kf.y);
                kh[2 * i + 1] = __floats2half2_rn(kf.z, kf.w);
                float4 vf = vsrc[i];
                vh[2 * i]     = __floats2half2_rn(vf.x, vf.y);
                vh[2 * i + 1] = __floats2half2_rn(vf.z, vf.w);
            }
            uint4* kdst = reinterpret_cast<uint4*>(&sK[srow * LDH + shalf * 32]);
            uint4* vdst = reinterpret_cast<uint4*>(&sV[srow * LDH + shalf * 32]);
            #pragma unroll
            for (int j = 0; j < 4; j++) {
                kdst[j] = reinterpret_cast<uint4*>(kh)[j];
                vdst[j] = reinterpret_cast<uint4*>(vh)[j];
            }
        }
        __syncthreads();

        // ---- S = Q @ K^T : 4 k16-steps; B-frags 2 n-tiles per ldmatrix.x4
        float acc[8][4];
        #pragma unroll
        for (int n = 0; n < 8; n++)
            #pragma unroll
            for (int j = 0; j < 4; j++) acc[n][j] = 0.f;

        #pragma unroll
        for (int ks = 0; ks < 4; ks++) {
            const int k0 = ks * 16;
            uint32_t a0, a1, a2, a3;
            uint32_t aaddr = (uint32_t)__cvta_generic_to_shared(
                &sQ[(mbase + lrow) * LDH + k0 + lcol]);
            LDM_X4(a0, a1, a2, a3, aaddr);
            #pragma unroll
            for (int np = 0; np < 4; np++) {
                uint32_t r0, r1, r2, r3;
                uint32_t baddr = (uint32_t)__cvta_generic_to_shared(
                    &sK[(np * 16 + lrow) * LDH + k0 + lcol]);
                LDM_X4(r0, r1, r2, r3, baddr);
                mma_fp16(acc[2 * np],     a0, a1, a2, a3, r0, r2);
                mma_fp16(acc[2 * np + 1], a0, a1, a2, a3, r1, r3);
            }
        }

        // ---- Online softmax (rows ty4, ty4+8; quad xor 1,2 spans a row)
        float mx0 = -INFINITY, mx1 = -INFINITY;
        #pragma unroll
        for (int n = 0; n < 8; n++) {
            mx0 = fmaxf(mx0, fmaxf(acc[n][0], acc[n][1]));
            mx1 = fmaxf(mx1, fmaxf(acc[n][2], acc[n][3]));
        }
        mx0 = fmaxf(mx0, __shfl_xor_sync(0xffffffffu, mx0, 1));
        mx0 = fmaxf(mx0, __shfl_xor_sync(0xffffffffu, mx0, 2));
        mx1 = fmaxf(mx1, __shfl_xor_sync(0xffffffffu, mx1, 1));
        mx1 = fmaxf(mx1, __shfl_xor_sync(0xffffffffu, mx1, 2));

        const float mn0 = fmaxf(m_run[0], mx0);
        const float mn1 = fmaxf(m_run[1], mx1);
        const float al0 = __expf(m_run[0] - mn0);
        const float al1 = __expf(m_run[1] - mn1);

        uint32_t pa[8], pb[8];   // A-frags of P: pa = rows ty4, pb = rows ty4+8
        float sum0 = 0.f, sum1 = 0.f;
        #pragma unroll
        for (int n = 0; n < 8; n++) {
            float p0 = __expf(acc[n][0] - mn0);
            float p1 = __expf(acc[n][1] - mn0);
            float p2 = __expf(acc[n][2] - mn1);
            float p3 = __expf(acc[n][3] - mn1);
            sum0 += p0 + p1;
            sum1 += p2 + p3;
            pa[n] = h2u(__floats2half2_rn(p0, p1));
            pb[n] = h2u(__floats2half2_rn(p2, p3));
        }
        sum0 += __shfl_xor_sync(0xffffffffu, sum0, 1);
        sum0 += __shfl_xor_sync(0xffffffffu, sum0, 2);
        sum1 += __shfl_xor_sync(0xffffffffu, sum1, 1);
        sum1 += __shfl_xor_sync(0xffffffffu, sum1, 2);

        l_run[0] = l_run[0] * al0 + sum0;  m_run[0] = mn0;
        l_run[1] = l_run[1] * al1 + sum1;  m_run[1] = mn1;

        #pragma unroll
        for (int n = 0; n < 8; n++) {
            acc_o[n][0] *= al0;  acc_o[n][1] *= al0;
            acc_o[n][2] *= al1;  acc_o[n][3] *= al1;
        }

        // ---- O += P @ V : A-frags direct from registers, B via ldmatrix.trans
        #pragma unroll
        for (int ks = 0; ks < 4; ks++) {
            const int k0 = ks * 16;
            const uint32_t a0 = pa[2 * ks],     a1 = pb[2 * ks];
            const uint32_t a2 = pa[2 * ks + 1], a3 = pb[2 * ks + 1];
            #pragma unroll
            for (int dp = 0; dp < 4; dp++) {
                uint32_t r0, r1, r2, r3;
                uint32_t vaddr = (uint32_t)__cvta_generic_to_shared(
                    &sV[(k0 + lrow) * LDH + dp * 16 + lcol]);
                LDM_X4T(r0, r1, r2, r3, vaddr);
                mma_fp16(acc_o[2 * dp],     a0, a1, a2, a3, r0, r1);
                mma_fp16(acc_o[2 * dp + 1], a0, a1, a2, a3, r2, r3);
            }
        }
    }

    // ---- Epilogue
    const int ty4 = lane >> 2, tx4 = lane & 3;
    const float inv0 = 1.f / l_run[0];
    const float inv1 = 1.f / l_run[1];
    const int r0 = q0 + mbase + ty4;
    float* O0 = Out + ((size_t)(b * Ll + r0)     * Hh + h) * Dd;
    float* O1 = Out + ((size_t)(b * Ll + r0 + 8) * Hh + h) * Dd;
    #pragma unroll
    for (int n = 0; n < 8; n++) {
        const int col = n * 8 + 2 * tx4;
        float2 v0; v0.x = acc_o[n][0] * inv0; v0.y = acc_o[n][1] * inv0;
        *reinterpret_cast<float2*>(O0 + col) = v0;
        float2 v1; v1.x = acc_o[n][2] * inv1; v1.y = acc_o[n][3] * inv1;
        *reinterpret_cast<float2*>(O1 + col) = v1;
    }
}

extern "C" void kernel_launch(void* const* d_in, const int* in_sizes, int n_in,
                              void* d_out, int out_size)
{
    const float* Q = (const float*)d_in[0];
    const float* K = (const float*)d_in[1];
    const float* V = (const float*)d_in[2];
    float* Out = (float*)d_out;

    dim3 grid(Ll / BM, Hh, Bb);   // (32, 8, 4); x-fastest -> same-(b,h) CTAs share K/V in L2
    flash_fp16<<<grid, 128>>>(Q, K, V, Out);
}